// round 2
// baseline (speedup 1.0000x reference)
#include <cuda_runtime.h>
#include <cuda_fp16.h>
#include <cstdint>

// ---------------- problem constants ----------------
#define MM      8192        // B*S
#define KD      4096        // D_IN
#define ND      4096        // D_OUT
#define RANK    32
#define KEXT    4128        // KD + RANK
#define HBS     128
#define INV_SQRT_HBS 0.08838834764831845f   // 1/sqrt(128)

// ---------------- device scratch (no malloc allowed) ----------------
__device__ __align__(16) __half g_Xext[(size_t)MM * KEXT];   // [8192,4128] fp16
__device__ __align__(16) __half g_Wext[(size_t)ND * KEXT];   // [4096,4128] fp16
__device__ __align__(16) float  g_A3[(size_t)RANK * KD];     // rotated lora_a

// ======================================================================
// P0a: A3[r,d] = S[d] * FWHT_128block(lora_a[r,:])[d] * (1/sqrt(128))
// ======================================================================
__global__ void mkA3_kernel(const float* __restrict__ la, const float* __restrict__ S) {
    __shared__ float row[KD];
    const int r = blockIdx.x;           // 0..31
    const int tid = threadIdx.x;        // 256 threads
    const float4* src = (const float4*)(la + (size_t)r * KD);
    for (int i = tid; i < KD / 4; i += 256)
        *(float4*)&row[i * 4] = src[i];
    __syncthreads();
    for (int str = 1; str < HBS; str <<= 1) {
        for (int p = tid; p < KD / 2; p += 256) {
            int blk = p >> 6, l = p & 63;
            int j  = ((l & ~(str - 1)) << 1) | (l & (str - 1));
            int i1 = blk * HBS + j, i2 = i1 + str;
            float a = row[i1], b = row[i2];
            row[i1] = a + b; row[i2] = a - b;
        }
        __syncthreads();
    }
    for (int i = tid; i < KD; i += 256)
        g_A3[(size_t)r * KD + i] = row[i] * INV_SQRT_HBS * S[i];
}

// ======================================================================
// P0b: Wext = [w_quantized | lora_b] as fp16
// ======================================================================
__global__ void convW_kernel(const float* __restrict__ w, const float* __restrict__ lb) {
    int idx = blockIdx.x * 256 + threadIdx.x;        // one 8-half chunk
    const int chunks_per_row = KEXT / 8;             // 516
    if (idx >= ND * chunks_per_row) return;
    int n = idx / chunks_per_row;
    int k = (idx - n * chunks_per_row) * 8;
    const float* src = (k < KD) ? (w + (size_t)n * KD + k)
                                : (lb + (size_t)n * RANK + (k - KD));
    float4 f0 = *(const float4*)(src);
    float4 f1 = *(const float4*)(src + 4);
    __half h[8];
    h[0]=__float2half_rn(f0.x); h[1]=__float2half_rn(f0.y);
    h[2]=__float2half_rn(f0.z); h[3]=__float2half_rn(f0.w);
    h[4]=__float2half_rn(f1.x); h[5]=__float2half_rn(f1.y);
    h[6]=__float2half_rn(f1.z); h[7]=__float2half_rn(f1.w);
    *(uint4*)(&g_Wext[(size_t)n * KEXT + k]) = *(uint4*)h;
}

// ======================================================================
// P1: per row: sign flip, blockwise FWHT, NVFP4 fake-quant -> fp16 Xext
// ======================================================================
__global__ void rotq_kernel(const float* __restrict__ x, const float* __restrict__ S) {
    __shared__ float row[KD];
    const int r = blockIdx.x;           // 0..8191
    const int tid = threadIdx.x;        // 256
    const float4* xv = (const float4*)(x + (size_t)r * KD);
    const float4* sv = (const float4*)S;
    for (int i = tid; i < KD / 4; i += 256) {
        float4 a = xv[i], s = sv[i];
        float4 o = make_float4(a.x * s.x, a.y * s.y, a.z * s.z, a.w * s.w);
        *(float4*)&row[i * 4] = o;
    }
    __syncthreads();
    for (int str = 1; str < HBS; str <<= 1) {
        for (int p = tid; p < KD / 2; p += 256) {
            int blk = p >> 6, l = p & 63;
            int j  = ((l & ~(str - 1)) << 1) | (l & (str - 1));
            int i1 = blk * HBS + j, i2 = i1 + str;
            float a = row[i1], b = row[i2];
            row[i1] = a + b; row[i2] = a - b;
        }
        __syncthreads();
    }
    // quantize: one 16-elem block per thread (4096/16 = 256)
    const int base = tid * 16;
    float v[16];
    float amax = 0.0f;
#pragma unroll
    for (int i = 0; i < 16; i += 4) {
        float4 t4 = *(float4*)&row[base + i];
        v[i+0] = t4.x * INV_SQRT_HBS; v[i+1] = t4.y * INV_SQRT_HBS;
        v[i+2] = t4.z * INV_SQRT_HBS; v[i+3] = t4.w * INV_SQRT_HBS;
    }
#pragma unroll
    for (int i = 0; i < 16; i++) amax = fmaxf(amax, fabsf(v[i]));
    amax = fmaxf(amax, 1e-12f);
    const float scale = amax / 6.0f;
    union { __half h[16]; uint4 u[2]; } buf;
#pragma unroll
    for (int i = 0; i < 16; i++) {
        float av = fabsf(v[i]) / scale;           // IEEE fp32 div, matches ref
        float level;
        if      (av <= 0.25f) level = 0.0f;
        else if (av <= 0.75f) level = 0.5f;
        else if (av <= 1.25f) level = 1.0f;
        else if (av <= 1.75f) level = 1.5f;
        else if (av <= 2.50f) level = 2.0f;
        else if (av <= 3.50f) level = 3.0f;
        else if (av <= 5.00f) level = 4.0f;
        else                  level = 6.0f;
        float q = copysignf(level * scale, v[i]);
        buf.h[i] = __float2half_rn(q);
    }
    uint4* dst = (uint4*)&g_Xext[(size_t)r * KEXT + base];
    dst[0] = buf.u[0];
    dst[1] = buf.u[1];
}

// ======================================================================
// P2: t = x @ A3^T  (uses raw x; algebraically == x_rot @ lora_a^T)
//     writes fp16 into Xext[:, 4096:4128]
// ======================================================================
__global__ void lorat_kernel(const float* __restrict__ x) {
    __shared__ float xs[64][32];
    __shared__ float a3s[32][33];
    const int tid = threadIdx.x;          // 256
    const int rb  = blockIdx.x * 64;      // 128 blocks
    const int rcol = tid & 31;            // LoRA rank index
    const int ig   = tid >> 5;            // row group 0..7 (8 rows each)
    float acc[8];
#pragma unroll
    for (int i = 0; i < 8; i++) acc[i] = 0.0f;

    for (int k0 = 0; k0 < KD; k0 += 32) {
        // x tile: 64 rows x 32 cols = 512 float4 chunks? -> 512 chunks of 4 floats
#pragma unroll
        for (int cc = 0; cc < 2; cc++) {
            int c = tid + cc * 256;        // 0..511
            int rr = c >> 3, q = c & 7;
            *(float4*)&xs[rr][q * 4] =
                *(const float4*)(x + (size_t)(rb + rr) * KD + k0 + q * 4);
        }
        {
            int rr = tid >> 3, q = tid & 7;
            float4 t4 = *(const float4*)(g_A3 + (size_t)rr * KD + k0 + q * 4);
            a3s[rr][q * 4 + 0] = t4.x; a3s[rr][q * 4 + 1] = t4.y;
            a3s[rr][q * 4 + 2] = t4.z; a3s[rr][q * 4 + 3] = t4.w;
        }
        __syncthreads();
#pragma unroll 8
        for (int kk = 0; kk < 32; kk++) {
            float av = a3s[rcol][kk];
#pragma unroll
            for (int i = 0; i < 8; i++)
                acc[i] += xs[ig * 8 + i][kk] * av;
        }
        __syncthreads();
    }
#pragma unroll
    for (int i = 0; i < 8; i++)
        g_Xext[(size_t)(rb + ig * 8 + i) * KEXT + KD + rcol] = __float2half_rn(acc[i]);
}

// ======================================================================
// P3: main GEMM  out[8192,4096] = Xext @ Wext^T + bias   (fp16 MMA, fp32 acc)
// ======================================================================
#define BM 128
#define BN 128
#define BK 32
#define SROW 40                       // padded smem row (halves): conflict-free ldmatrix
#define NTILES (KEXT / BK)            // 129

__device__ __forceinline__ void cp16(void* sm, const void* gm) {
    uint32_t s = (uint32_t)__cvta_generic_to_shared(sm);
    asm volatile("cp.async.cg.shared.global [%0], [%1], 16;\n" :: "r"(s), "l"(gm));
}
__device__ __forceinline__ void cp_commit() {
    asm volatile("cp.async.commit_group;\n");
}
__device__ __forceinline__ void cp_wait1() {
    asm volatile("cp.async.wait_group 1;\n");
}
__device__ __forceinline__ void cp_wait0() {
    asm volatile("cp.async.wait_group 0;\n");
}
__device__ __forceinline__ void ldm4(uint32_t* r, const void* p) {
    uint32_t a = (uint32_t)__cvta_generic_to_shared(p);
    asm volatile("ldmatrix.sync.aligned.m8n8.x4.shared.b16 {%0,%1,%2,%3}, [%4];"
        : "=r"(r[0]), "=r"(r[1]), "=r"(r[2]), "=r"(r[3]) : "r"(a));
}
__device__ __forceinline__ void mma16816(float* d, const uint32_t* a, uint32_t b0, uint32_t b1) {
    asm volatile("mma.sync.aligned.m16n8k16.row.col.f32.f16.f16.f32 "
        "{%0,%1,%2,%3},{%4,%5,%6,%7},{%8,%9},{%0,%1,%2,%3};"
        : "+f"(d[0]), "+f"(d[1]), "+f"(d[2]), "+f"(d[3])
        : "r"(a[0]), "r"(a[1]), "r"(a[2]), "r"(a[3]), "r"(b0), "r"(b1));
}

__global__ __launch_bounds__(256) void gemm_kernel(const float* __restrict__ bias,
                                                   float* __restrict__ out) {
    __shared__ __align__(16) __half sA[2][BM * SROW];
    __shared__ __align__(16) __half sB[2][BN * SROW];
    const int tid  = threadIdx.x;
    const int warp = tid >> 5, lane = tid & 31;
    const int wm = warp >> 1, wn = warp & 1;        // 4x2 warp grid
    const int rowBase = blockIdx.y * BM;
    const int colBase = blockIdx.x * BN;
    const __half* gA = g_Xext + (size_t)rowBase * KEXT;
    const __half* gB = g_Wext + (size_t)colBase * KEXT;

    float acc[2][8][4];
#pragma unroll
    for (int m = 0; m < 2; m++)
#pragma unroll
        for (int n = 0; n < 8; n++)
#pragma unroll
            for (int q = 0; q < 4; q++) acc[m][n][q] = 0.0f;

    // ldmatrix per-lane address components
    const int lrow = ((lane >> 3) & 1) * 8 + (lane & 7);
    const int lcol = (lane >> 4) * 8;

#define LOAD_TILE(stage, t)                                                     \
    do {                                                                        \
        int k0 = (t) * BK;                                                      \
        _Pragma("unroll")                                                       \
        for (int cc = 0; cc < 2; cc++) {                                        \
            int c = tid + cc * 256;                                             \
            int rr = c >> 2, q = c & 3;                                         \
            cp16(&sA[stage][rr * SROW + q * 8], gA + (size_t)rr * KEXT + k0 + q * 8); \
        }                                                                       \
        _Pragma("unroll")                                                       \
        for (int cc = 0; cc < 2; cc++) {                                        \
            int c = tid + cc * 256;                                             \
            int rr = c >> 2, q = c & 3;                                         \
            cp16(&sB[stage][rr * SROW + q * 8], gB + (size_t)rr * KEXT + k0 + q * 8); \
        }                                                                       \
        cp_commit();                                                            \
    } while (0)

    LOAD_TILE(0, 0);
    LOAD_TILE(1, 1);

    for (int t = 0; t < NTILES; t++) {
        if (t + 1 < NTILES) cp_wait1(); else cp_wait0();
        __syncthreads();
        const int st = t & 1;
#pragma unroll
        for (int kk = 0; kk < BK; kk += 16) {
            uint32_t afrag[2][4];
#pragma unroll
            for (int mt = 0; mt < 2; mt++)
                ldm4(afrag[mt], &sA[st][(wm * 32 + mt * 16 + lrow) * SROW + kk + lcol]);
            uint32_t bfrag[4][4];
#pragma unroll
            for (int p = 0; p < 4; p++)
                ldm4(bfrag[p], &sB[st][(wn * 64 + p * 16 + lrow) * SROW + kk + lcol]);
#pragma unroll
            for (int mt = 0; mt < 2; mt++)
#pragma unroll
                for (int p = 0; p < 4; p++) {
                    mma16816(acc[mt][2 * p + 0], afrag[mt], bfrag[p][0], bfrag[p][2]);
                    mma16816(acc[mt][2 * p + 1], afrag[mt], bfrag[p][1], bfrag[p][3]);
                }
        }
        __syncthreads();
        if (t + 2 < NTILES) LOAD_TILE(st, t + 2);
    }

    // epilogue: +bias, fp32 stores
#pragma unroll
    for (int mt = 0; mt < 2; mt++) {
#pragma unroll
        for (int nt = 0; nt < 8; nt++) {
            int m0 = rowBase + wm * 32 + mt * 16 + (lane >> 2);
            int n0 = colBase + wn * 64 + (nt >> 1) * 16 + (nt & 1) * 8 + (lane & 3) * 2;
            float b0 = bias[n0], b1 = bias[n0 + 1];
            float2 v0 = make_float2(acc[mt][nt][0] + b0, acc[mt][nt][1] + b1);
            float2 v1 = make_float2(acc[mt][nt][2] + b0, acc[mt][nt][3] + b1);
            *(float2*)(out + (size_t)m0 * ND + n0)       = v0;
            *(float2*)(out + (size_t)(m0 + 8) * ND + n0) = v1;
        }
    }
}

// ======================================================================
// launcher
// ======================================================================
extern "C" void kernel_launch(void* const* d_in, const int* in_sizes, int n_in,
                              void* d_out, int out_size) {
    const float* x    = (const float*)d_in[0];   // [8192,4096]
    const float* S    = (const float*)d_in[1];   // [4096]
    // d_in[2] = H_block (unused; FWHT computed analytically)
    const float* w    = (const float*)d_in[3];   // [4096,4096]
    const float* la   = (const float*)d_in[4];   // [32,4096]
    const float* lb   = (const float*)d_in[5];   // [4096,32]
    const float* bias = (const float*)d_in[6];   // [4096]
    float* out = (float*)d_out;

    mkA3_kernel<<<RANK, 256>>>(la, S);
    convW_kernel<<<(ND * (KEXT / 8) + 255) / 256, 256>>>(w, lb);
    rotq_kernel<<<MM, 256>>>(x, S);
    lorat_kernel<<<MM / 64, 256>>>(x);
    gemm_kernel<<<dim3(ND / BN, MM / BM), 256>>>(bias, out);
}

// round 5
// speedup vs baseline: 1.0473x; 1.0473x over previous
#include <cuda_runtime.h>
#include <cuda_fp16.h>
#include <cstdint>

// ---------------- problem constants ----------------
#define MM      8192        // B*S
#define KD      4096        // D_IN
#define ND      4096        // D_OUT
#define RANK    32
#define KEXTP   4160        // 4096 + 32 (lora) + 32 (zero pad) -> 130 chunks of 32
#define HBS     128
#define INV_SQRT_HBS 0.08838834764831845f

// ---------------- device scratch (.bss zero-init; pad cols stay 0) ----------
__device__ __align__(16) __half g_Xext[(size_t)MM * KEXTP];
__device__ __align__(16) __half g_Wext[(size_t)ND * KEXTP];
__device__ __align__(16) float  g_A3[(size_t)RANK * KD];

// ======================================================================
// P0a: A3[r,d] = S[d] * FWHT_128block(lora_a[r,:])[d] / sqrt(128)
// ======================================================================
__global__ void mkA3_kernel(const float* __restrict__ la, const float* __restrict__ S) {
    __shared__ float row[KD];
    const int r = blockIdx.x;
    const int tid = threadIdx.x;
    const float4* src = (const float4*)(la + (size_t)r * KD);
    for (int i = tid; i < KD / 4; i += 256)
        *(float4*)&row[i * 4] = src[i];
    __syncthreads();
    for (int str = 1; str < HBS; str <<= 1) {
        for (int p = tid; p < KD / 2; p += 256) {
            int blk = p >> 6, l = p & 63;
            int j  = ((l & ~(str - 1)) << 1) | (l & (str - 1));
            int i1 = blk * HBS + j, i2 = i1 + str;
            float a = row[i1], b = row[i2];
            row[i1] = a + b; row[i2] = a - b;
        }
        __syncthreads();
    }
    for (int i = tid; i < KD; i += 256)
        g_A3[(size_t)r * KD + i] = row[i] * INV_SQRT_HBS * S[i];
}

// ======================================================================
// P0b: Wext = [w_quantized | lora_b] as fp16 (pad cols remain zero)
// ======================================================================
__global__ void convW_kernel(const float* __restrict__ w, const float* __restrict__ lb) {
    int idx = blockIdx.x * 256 + threadIdx.x;
    const int chunks_per_row = 516;              // (4096+32)/8
    if (idx >= ND * chunks_per_row) return;
    int n = idx / chunks_per_row;
    int k = (idx - n * chunks_per_row) * 8;
    const float* src = (k < KD) ? (w + (size_t)n * KD + k)
                                : (lb + (size_t)n * RANK + (k - KD));
    float4 f0 = *(const float4*)(src);
    float4 f1 = *(const float4*)(src + 4);
    __half h[8];
    h[0]=__float2half_rn(f0.x); h[1]=__float2half_rn(f0.y);
    h[2]=__float2half_rn(f0.z); h[3]=__float2half_rn(f0.w);
    h[4]=__float2half_rn(f1.x); h[5]=__float2half_rn(f1.y);
    h[6]=__float2half_rn(f1.z); h[7]=__float2half_rn(f1.w);
    *(uint4*)(&g_Wext[(size_t)n * KEXTP + k]) = *(uint4*)h;
}

// ======================================================================
// P1: warp-per-128-block FWHT in registers (shfl.bfly), NVFP4 quant
// ======================================================================
__global__ __launch_bounds__(256) void rotq2(const float* __restrict__ x,
                                             const float* __restrict__ S) {
    const int r = blockIdx.x;
    const int w = threadIdx.x >> 5, lane = threadIdx.x & 31;
    const float* xr = x + (size_t)r * KD;
    __half* orow = g_Xext + (size_t)r * KEXTP;
#pragma unroll
    for (int hbi = 0; hbi < 4; hbi++) {
        const int base = (w * 4 + hbi) * HBS;
        float v[4];
#pragma unroll
        for (int i = 0; i < 4; i++) {
            int e = base + i * 32 + lane;
            v[i] = xr[e] * S[e];
        }
#pragma unroll
        for (int str = 1; str <= 16; str <<= 1) {
#pragma unroll
            for (int i = 0; i < 4; i++) {
                float o = __shfl_xor_sync(0xffffffffu, v[i], str);
                v[i] = (lane & str) ? (o - v[i]) : (v[i] + o);
            }
        }
        { float a=v[0],b=v[1]; v[0]=a+b; v[1]=a-b;
          float c=v[2],d=v[3]; v[2]=c+d; v[3]=c-d; }
        { float a=v[0],c=v[2]; v[0]=a+c; v[2]=a-c;
          float b=v[1],d=v[3]; v[1]=b+d; v[3]=b-d; }
#pragma unroll
        for (int i = 0; i < 4; i++) v[i] *= INV_SQRT_HBS;
#pragma unroll
        for (int i = 0; i < 4; i++) {
            float m = fabsf(v[i]);
#pragma unroll
            for (int str = 1; str <= 8; str <<= 1)
                m = fmaxf(m, __shfl_xor_sync(0xffffffffu, m, str));
            m = fmaxf(m, 1e-12f);
            float scale = m / 6.0f;
            float av = fabsf(v[i]) / scale;
            float level;
            if      (av <= 0.25f) level = 0.0f;
            else if (av <= 0.75f) level = 0.5f;
            else if (av <= 1.25f) level = 1.0f;
            else if (av <= 1.75f) level = 1.5f;
            else if (av <= 2.50f) level = 2.0f;
            else if (av <= 3.50f) level = 3.0f;
            else if (av <= 5.00f) level = 4.0f;
            else                  level = 6.0f;
            float q = copysignf(level * scale, v[i]);
            orow[base + i * 32 + lane] = __float2half_rn(q);
        }
    }
}

// ======================================================================
// P2: t = x @ A3^T -> Xext[:, 4096:4128].  16 rows/block, grid 512.
// ======================================================================
__global__ __launch_bounds__(256) void lorat2(const float* __restrict__ x) {
    __shared__ float xs[16][64];
    __shared__ float a3s[32][65];
    const int tid = threadIdx.x;
    const int rb  = blockIdx.x * 16;
    const int j = tid & 31, g = tid >> 5;
    float acc0 = 0.0f, acc1 = 0.0f;
    for (int k0 = 0; k0 < KD; k0 += 64) {
        { int row = tid >> 4, q = tid & 15;
          *(float4*)&xs[row][q * 4] =
              *(const float4*)(x + (size_t)(rb + row) * KD + k0 + q * 4); }
#pragma unroll
        for (int i = 0; i < 2; i++) {
            int c = tid + i * 256; int row = c >> 4, q = c & 15;
            float4 t4 = *(const float4*)(g_A3 + (size_t)row * KD + k0 + q * 4);
            a3s[row][q*4+0]=t4.x; a3s[row][q*4+1]=t4.y;
            a3s[row][q*4+2]=t4.z; a3s[row][q*4+3]=t4.w;
        }
        __syncthreads();
#pragma unroll 16
        for (int k = 0; k < 64; k++) {
            float a = a3s[j][k];
            acc0 += xs[g * 2 + 0][k] * a;
            acc1 += xs[g * 2 + 1][k] * a;
        }
        __syncthreads();
    }
    g_Xext[(size_t)(rb + g * 2 + 0) * KEXTP + KD + j] = __float2half_rn(acc0);
    g_Xext[(size_t)(rb + g * 2 + 1) * KEXTP + KD + j] = __float2half_rn(acc1);
}

// ======================================================================
// P3: GEMM out[8192,4096] = Xext @ Wext^T + bias
//     128x256 CTA tile, BK=32, 4-stage cp.async, 8 warps of 64x64
// ======================================================================
#define BM 128
#define BN 256
#define BK 32
#define STAGES 4
#define SROW 40                              // padded row in halves
#define NT (KEXTP / BK)                      // 130
#define ASTG (BM * SROW)                     // halves per A stage (5120)
#define BSTG (BN * SROW)                     // halves per B stage (10240)
#define STG  (ASTG + BSTG)                   // 15360 halves = 30720 B
#define GEMM_SMEM (STAGES * STG * 2)         // 122880 B

__device__ __forceinline__ void cp16s(uint32_t saddr, const void* gaddr) {
    asm volatile("cp.async.cg.shared.global [%0], [%1], 16;" :: "r"(saddr), "l"(gaddr));
}
__device__ __forceinline__ void ldm4(uint32_t* r, uint32_t a) {
    asm volatile("ldmatrix.sync.aligned.m8n8.x4.shared.b16 {%0,%1,%2,%3}, [%4];"
        : "=r"(r[0]), "=r"(r[1]), "=r"(r[2]), "=r"(r[3]) : "r"(a));
}
__device__ __forceinline__ void mma16816(float* d, const uint32_t* a, uint32_t b0, uint32_t b1) {
    asm volatile("mma.sync.aligned.m16n8k16.row.col.f32.f16.f16.f32 "
        "{%0,%1,%2,%3},{%4,%5,%6,%7},{%8,%9},{%0,%1,%2,%3};"
        : "+f"(d[0]), "+f"(d[1]), "+f"(d[2]), "+f"(d[3])
        : "r"(a[0]), "r"(a[1]), "r"(a[2]), "r"(a[3]), "r"(b0), "r"(b1));
}

__global__ __launch_bounds__(256, 1) void gemm_hmma(const float* __restrict__ bias,
                                                    float* __restrict__ out) {
    extern __shared__ __half smem[];
    const int tid  = threadIdx.x;
    const int warp = tid >> 5, lane = tid & 31;
    const int wm = warp >> 2, wn = warp & 3;          // 2 x 4 warp grid
    const int mbase = blockIdx.y * BM;
    const int nbase = blockIdx.x * BN;
    const __half* gA = g_Xext + (size_t)mbase * KEXTP;
    const __half* gB = g_Wext + (size_t)nbase * KEXTP;
    const uint32_t sbase = (uint32_t)__cvta_generic_to_shared(smem);

    float acc[4][8][4];
#pragma unroll
    for (int a = 0; a < 4; a++)
#pragma unroll
        for (int b = 0; b < 8; b++)
#pragma unroll
            for (int c = 0; c < 4; c++) acc[a][b][c] = 0.0f;

    const int lrow = ((lane >> 3) & 1) * 8 + (lane & 7);
    const int lcol = (lane >> 4) * 8;

    // per-thread load coordinates
    const int arow0 = tid >> 2, aq = tid & 3;          // +64 rows for i=1

#define LOAD_STAGE(sg, t)                                                        \
    do {                                                                         \
        const int k0 = (t) * BK;                                                 \
        const uint32_t ab = sbase + (uint32_t)((sg) * STG) * 2;                  \
        const uint32_t bb = ab + ASTG * 2;                                       \
        _Pragma("unroll")                                                        \
        for (int i = 0; i < 2; i++) {                                            \
            int row = arow0 + i * 64;                                            \
            cp16s(ab + (uint32_t)(row * SROW + aq * 8) * 2,                      \
                  gA + (size_t)row * KEXTP + k0 + aq * 8);                       \
        }                                                                        \
        _Pragma("unroll")                                                        \
        for (int i = 0; i < 4; i++) {                                            \
            int row = arow0 + i * 64;                                            \
            cp16s(bb + (uint32_t)(row * SROW + aq * 8) * 2,                      \
                  gB + (size_t)row * KEXTP + k0 + aq * 8);                       \
        }                                                                        \
        asm volatile("cp.async.commit_group;");                                  \
    } while (0)

    LOAD_STAGE(0, 0);
    LOAD_STAGE(1, 1);
    LOAD_STAGE(2, 2);

    for (int t = 0; t < NT; t++) {
        if (t + 2 < NT)      asm volatile("cp.async.wait_group 2;");
        else if (t + 1 < NT) asm volatile("cp.async.wait_group 1;");
        else                 asm volatile("cp.async.wait_group 0;");
        __syncthreads();
        if (t + 3 < NT) LOAD_STAGE((t + 3) & 3, t + 3);

        const int sg = t & 3;
        const uint32_t ab = sbase + (uint32_t)(sg * STG) * 2;
        const uint32_t bb = ab + ASTG * 2;
#pragma unroll
        for (int kk = 0; kk < BK; kk += 16) {
            uint32_t af[4][4];
#pragma unroll
            for (int mt = 0; mt < 4; mt++)
                ldm4(af[mt], ab + (uint32_t)((wm * 64 + mt * 16 + lrow) * SROW + kk + lcol) * 2);
            uint32_t bf[4][4];
#pragma unroll
            for (int p = 0; p < 4; p++)
                ldm4(bf[p], bb + (uint32_t)((wn * 64 + p * 16 + lrow) * SROW + kk + lcol) * 2);
#pragma unroll
            for (int mt = 0; mt < 4; mt++)
#pragma unroll
                for (int p = 0; p < 4; p++) {
                    mma16816(acc[mt][2 * p + 0], af[mt], bf[p][0], bf[p][2]);
                    mma16816(acc[mt][2 * p + 1], af[mt], bf[p][1], bf[p][3]);
                }
        }
        __syncthreads();
    }

    // epilogue: +bias, fp32 stores
#pragma unroll
    for (int mt = 0; mt < 4; mt++) {
#pragma unroll
        for (int nt = 0; nt < 8; nt++) {
            int m0 = mbase + wm * 64 + mt * 16 + (lane >> 2);
            int n0 = nbase + wn * 64 + nt * 8 + (lane & 3) * 2;
            float b0 = bias[n0], b1 = bias[n0 + 1];
            float2 v0 = make_float2(acc[mt][nt][0] + b0, acc[mt][nt][1] + b1);
            float2 v1 = make_float2(acc[mt][nt][2] + b0, acc[mt][nt][3] + b1);
            *(float2*)(out + (size_t)m0 * ND + n0)       = v0;
            *(float2*)(out + (size_t)(m0 + 8) * ND + n0) = v1;
        }
    }
}

// ======================================================================
// launcher
// ======================================================================
extern "C" void kernel_launch(void* const* d_in, const int* in_sizes, int n_in,
                              void* d_out, int out_size) {
    const float* x    = (const float*)d_in[0];
    const float* S    = (const float*)d_in[1];
    // d_in[2] = H_block (unused; FWHT computed analytically)
    const float* w    = (const float*)d_in[3];
    const float* la   = (const float*)d_in[4];
    const float* lb   = (const float*)d_in[5];
    const float* bias = (const float*)d_in[6];
    float* out = (float*)d_out;

    static int inited = 0;
    if (!inited) {
        cudaFuncSetAttribute(gemm_hmma, cudaFuncAttributeMaxDynamicSharedMemorySize, GEMM_SMEM);
        inited = 1;
    }

    mkA3_kernel<<<RANK, 256>>>(la, S);
    convW_kernel<<<(ND * 516 + 255) / 256, 256>>>(w, lb);
    rotq2<<<MM, 256>>>(x, S);
    lorat2<<<MM / 16, 256>>>(x);
    gemm_hmma<<<dim3(ND / BN, MM / BM), 256, GEMM_SMEM>>>(bias, out);
}

// round 6
// speedup vs baseline: 1.1997x; 1.1456x over previous
#include <cuda_runtime.h>
#include <cuda_fp16.h>
#include <cstdint>

// ---------------- problem constants ----------------
#define MM      8192        // B*S
#define KD      4096        // D_IN
#define ND      4096        // D_OUT
#define RANK    32
#define KEXTP   4160        // 4096 + 32 (lora) + 32 (zero pad) -> 65 chunks of 64
#define HBS     128
#define INV_SQRT_HBS 0.08838834764831845f

// ---------------- device scratch (.bss zero-init; pad cols stay 0) ----------
__device__ __align__(16) __half g_Xext[(size_t)MM * KEXTP];
__device__ __align__(16) __half g_Wext[(size_t)ND * KEXTP];
__device__ __align__(16) float  g_A3T[(size_t)KD * RANK];   // k-major rotated lora_a

// ======================================================================
// P0a: A3T[d][r] = S[d] * FWHT_128block(lora_a[r,:])[d] / sqrt(128)
// ======================================================================
__global__ void mkA3_kernel(const float* __restrict__ la, const float* __restrict__ S) {
    __shared__ float row[KD];
    const int r = blockIdx.x;
    const int tid = threadIdx.x;
    const float4* src = (const float4*)(la + (size_t)r * KD);
    for (int i = tid; i < KD / 4; i += 256)
        *(float4*)&row[i * 4] = src[i];
    __syncthreads();
    for (int str = 1; str < HBS; str <<= 1) {
        for (int p = tid; p < KD / 2; p += 256) {
            int blk = p >> 6, l = p & 63;
            int j  = ((l & ~(str - 1)) << 1) | (l & (str - 1));
            int i1 = blk * HBS + j, i2 = i1 + str;
            float a = row[i1], b = row[i2];
            row[i1] = a + b; row[i2] = a - b;
        }
        __syncthreads();
    }
    for (int i = tid; i < KD; i += 256)
        g_A3T[(size_t)i * RANK + r] = row[i] * INV_SQRT_HBS * S[i];
}

// ======================================================================
// P0b: Wext = [w_quantized | lora_b] as fp16 (pad cols remain zero)
// ======================================================================
__global__ void convW_kernel(const float* __restrict__ w, const float* __restrict__ lb) {
    int idx = blockIdx.x * 256 + threadIdx.x;
    const int chunks_per_row = 516;              // (4096+32)/8
    if (idx >= ND * chunks_per_row) return;
    int n = idx / chunks_per_row;
    int k = (idx - n * chunks_per_row) * 8;
    const float* src = (k < KD) ? (w + (size_t)n * KD + k)
                                : (lb + (size_t)n * RANK + (k - KD));
    float4 f0 = *(const float4*)(src);
    float4 f1 = *(const float4*)(src + 4);
    __half h[8];
    h[0]=__float2half_rn(f0.x); h[1]=__float2half_rn(f0.y);
    h[2]=__float2half_rn(f0.z); h[3]=__float2half_rn(f0.w);
    h[4]=__float2half_rn(f1.x); h[5]=__float2half_rn(f1.y);
    h[6]=__float2half_rn(f1.z); h[7]=__float2half_rn(f1.w);
    *(uint4*)(&g_Wext[(size_t)n * KEXTP + k]) = *(uint4*)h;
}

// ======================================================================
// P1: warp-per-128-block FWHT in registers (shfl.bfly), NVFP4 quant
// ======================================================================
__global__ __launch_bounds__(256) void rotq2(const float* __restrict__ x,
                                             const float* __restrict__ S) {
    const int r = blockIdx.x;
    const int w = threadIdx.x >> 5, lane = threadIdx.x & 31;
    const float* xr = x + (size_t)r * KD;
    __half* orow = g_Xext + (size_t)r * KEXTP;
#pragma unroll
    for (int hbi = 0; hbi < 4; hbi++) {
        const int base = (w * 4 + hbi) * HBS;
        float v[4];
#pragma unroll
        for (int i = 0; i < 4; i++) {
            int e = base + i * 32 + lane;
            v[i] = xr[e] * S[e];
        }
#pragma unroll
        for (int str = 1; str <= 16; str <<= 1) {
#pragma unroll
            for (int i = 0; i < 4; i++) {
                float o = __shfl_xor_sync(0xffffffffu, v[i], str);
                v[i] = (lane & str) ? (o - v[i]) : (v[i] + o);
            }
        }
        { float a=v[0],b=v[1]; v[0]=a+b; v[1]=a-b;
          float c=v[2],d=v[3]; v[2]=c+d; v[3]=c-d; }
        { float a=v[0],c=v[2]; v[0]=a+c; v[2]=a-c;
          float b=v[1],d=v[3]; v[1]=b+d; v[3]=b-d; }
#pragma unroll
        for (int i = 0; i < 4; i++) v[i] *= INV_SQRT_HBS;
#pragma unroll
        for (int i = 0; i < 4; i++) {
            float m = fabsf(v[i]);
#pragma unroll
            for (int str = 1; str <= 8; str <<= 1)
                m = fmaxf(m, __shfl_xor_sync(0xffffffffu, m, str));
            m = fmaxf(m, 1e-12f);
            float scale = m / 6.0f;
            float av = fabsf(v[i]) / scale;
            float level;
            if      (av <= 0.25f) level = 0.0f;
            else if (av <= 0.75f) level = 0.5f;
            else if (av <= 1.25f) level = 1.0f;
            else if (av <= 1.75f) level = 1.5f;
            else if (av <= 2.50f) level = 2.0f;
            else if (av <= 3.50f) level = 3.0f;
            else if (av <= 5.00f) level = 4.0f;
            else                  level = 6.0f;
            float q = copysignf(level * scale, v[i]);
            orow[base + i * 32 + lane] = __float2half_rn(q);
        }
    }
}

// ======================================================================
// P2: t = x @ A3^T -> Xext[:, 4096:4128]
//     32 rows/block (grid 256), 4-way K split, 4 rows x 4 ranks / thread
// ======================================================================
#define CHK  512
#define XSTR 516                       // floats per smem row (516/4=129 odd)
#define LORAT_SMEM (32 * XSTR * 4)     // 66048 B

__global__ __launch_bounds__(256) void lorat3(const float* __restrict__ x) {
    extern __shared__ float sm[];
    const int tid = threadIdx.x;
    const int rb  = blockIdx.x * 32;
    const int ksq = tid >> 6;              // k-quarter 0..3
    const int rem = tid & 63;
    const int rg4 = (rem & 7) * 4;         // rank base (4 ranks)
    const int rowg = rem >> 3;             // 0..7; rows rowg + 8*rr
    const float4* A3T4 = (const float4*)g_A3T;   // [k][8] float4

    float acc[4][4];
#pragma unroll
    for (int a = 0; a < 4; a++)
#pragma unroll
        for (int b = 0; b < 4; b++) acc[a][b] = 0.0f;

    for (int c0 = 0; c0 < KD; c0 += CHK) {
        // stage 32 rows x 512 k
#pragma unroll
        for (int i = 0; i < 16; i++) {
            int c = tid + i * 256;
            int row = c >> 7, q = c & 127;
            *(float4*)&sm[row * XSTR + q * 4] =
                *(const float4*)(x + (size_t)(rb + row) * KD + c0 + q * 4);
        }
        __syncthreads();
        const int kb = ksq * 128;
#pragma unroll 4
        for (int k4 = 0; k4 < 32; k4++) {
            const int kk0 = kb + k4 * 4;
            float4 xv[4];
#pragma unroll
            for (int rr = 0; rr < 4; rr++)
                xv[rr] = *(float4*)&sm[(rowg + 8 * rr) * XSTR + kk0];
#pragma unroll
            for (int j = 0; j < 4; j++) {
                float4 av = __ldg(&A3T4[(size_t)(c0 + kk0 + j) * 8 + (rg4 >> 2)]);
#pragma unroll
                for (int rr = 0; rr < 4; rr++) {
                    float xe = ((const float*)&xv[rr])[j];
                    acc[rr][0] += xe * av.x;
                    acc[rr][1] += xe * av.y;
                    acc[rr][2] += xe * av.z;
                    acc[rr][3] += xe * av.w;
                }
            }
        }
        __syncthreads();
    }
    // cross-K-quarter reduction in smem (reuse xs region)
#pragma unroll
    for (int rr = 0; rr < 4; rr++)
#pragma unroll
        for (int j = 0; j < 4; j++)
            sm[ksq * 1024 + (rowg + 8 * rr) * 32 + rg4 + j] = acc[rr][j];
    __syncthreads();
    {
        const int row = tid >> 3;
        const int rkb = (tid & 7) * 4;
        float s[4];
#pragma unroll
        for (int j = 0; j < 4; j++)
            s[j] = sm[row * 32 + rkb + j]        + sm[1024 + row * 32 + rkb + j]
                 + sm[2048 + row * 32 + rkb + j] + sm[3072 + row * 32 + rkb + j];
        __half h[4];
        h[0] = __float2half_rn(s[0]); h[1] = __float2half_rn(s[1]);
        h[2] = __float2half_rn(s[2]); h[3] = __float2half_rn(s[3]);
        *(uint2*)&g_Xext[(size_t)(rb + row) * KEXTP + KD + rkb] = *(uint2*)h;
    }
}

// ======================================================================
// P3: GEMM out[8192,4096] = Xext @ Wext^T + bias
//     128x256 CTA tile, BK=64, 3-stage cp.async, 8 warps of 64x64
// ======================================================================
#define BM 128
#define BN 256
#define BK 64
#define STAGES 3
#define SROW 72                              // padded row in halves (9 units odd)
#define NT (KEXTP / BK)                      // 65
#define ASTG (BM * SROW)                     // 9216 halves
#define BSTG (BN * SROW)                     // 18432 halves
#define STG  (ASTG + BSTG)                   // 27648 halves = 55296 B
#define GEMM_SMEM (STAGES * STG * 2)         // 165888 B

__device__ __forceinline__ void cp16s(uint32_t saddr, const void* gaddr) {
    asm volatile("cp.async.cg.shared.global [%0], [%1], 16;" :: "r"(saddr), "l"(gaddr));
}
__device__ __forceinline__ void ldm4(uint32_t* r, uint32_t a) {
    asm volatile("ldmatrix.sync.aligned.m8n8.x4.shared.b16 {%0,%1,%2,%3}, [%4];"
        : "=r"(r[0]), "=r"(r[1]), "=r"(r[2]), "=r"(r[3]) : "r"(a));
}
__device__ __forceinline__ void mma16816(float* d, const uint32_t* a, uint32_t b0, uint32_t b1) {
    asm volatile("mma.sync.aligned.m16n8k16.row.col.f32.f16.f16.f32 "
        "{%0,%1,%2,%3},{%4,%5,%6,%7},{%8,%9},{%0,%1,%2,%3};"
        : "+f"(d[0]), "+f"(d[1]), "+f"(d[2]), "+f"(d[3])
        : "r"(a[0]), "r"(a[1]), "r"(a[2]), "r"(a[3]), "r"(b0), "r"(b1));
}

__global__ __launch_bounds__(256, 1) void gemm_hmma(const float* __restrict__ bias,
                                                    float* __restrict__ out) {
    extern __shared__ __half smemh[];
    const int tid  = threadIdx.x;
    const int warp = tid >> 5, lane = tid & 31;
    const int wm = warp >> 2, wn = warp & 3;          // 2 x 4 warp grid
    const int mbase = blockIdx.y * BM;
    const int nbase = blockIdx.x * BN;
    const __half* gA = g_Xext + (size_t)mbase * KEXTP;
    const __half* gB = g_Wext + (size_t)nbase * KEXTP;
    const uint32_t sbase = (uint32_t)__cvta_generic_to_shared(smemh);

    float acc[4][8][4];
#pragma unroll
    for (int a = 0; a < 4; a++)
#pragma unroll
        for (int b = 0; b < 8; b++)
#pragma unroll
            for (int c = 0; c < 4; c++) acc[a][b][c] = 0.0f;

    const int lrow = ((lane >> 3) & 1) * 8 + (lane & 7);
    const int lcol = (lane >> 4) * 8;

#define LOAD_STAGE(sg, t)                                                        \
    do {                                                                         \
        const int k0 = (t) * BK;                                                 \
        const uint32_t ab = sbase + (uint32_t)((sg) * STG) * 2;                  \
        const uint32_t bb = ab + ASTG * 2;                                       \
        _Pragma("unroll")                                                        \
        for (int i = 0; i < 4; i++) {                                            \
            int c = tid + i * 256;                                               \
            int row = c >> 3, q = c & 7;                                         \
            cp16s(ab + (uint32_t)(row * SROW + q * 8) * 2,                       \
                  gA + (size_t)row * KEXTP + k0 + q * 8);                        \
        }                                                                        \
        _Pragma("unroll")                                                        \
        for (int i = 0; i < 8; i++) {                                            \
            int c = tid + i * 256;                                               \
            int row = c >> 3, q = c & 7;                                         \
            cp16s(bb + (uint32_t)(row * SROW + q * 8) * 2,                       \
                  gB + (size_t)row * KEXTP + k0 + q * 8);                        \
        }                                                                        \
        asm volatile("cp.async.commit_group;");                                  \
    } while (0)

    LOAD_STAGE(0, 0);
    LOAD_STAGE(1, 1);

    int st = 0;
    for (int t = 0; t < NT; t++) {
        if (t + 1 < NT) asm volatile("cp.async.wait_group 1;");
        else            asm volatile("cp.async.wait_group 0;");
        __syncthreads();
        if (t + 2 < NT) {
            int ns = st + 2; if (ns >= STAGES) ns -= STAGES;
            LOAD_STAGE(ns, t + 2);
        }
        const uint32_t ab = sbase + (uint32_t)(st * STG) * 2;
        const uint32_t bb = ab + ASTG * 2;
#pragma unroll
        for (int kk = 0; kk < BK; kk += 16) {
            uint32_t af[4][4];
#pragma unroll
            for (int mt = 0; mt < 4; mt++)
                ldm4(af[mt], ab + (uint32_t)((wm * 64 + mt * 16 + lrow) * SROW + kk + lcol) * 2);
            uint32_t bf[4][4];
#pragma unroll
            for (int p = 0; p < 4; p++)
                ldm4(bf[p], bb + (uint32_t)((wn * 64 + p * 16 + lrow) * SROW + kk + lcol) * 2);
#pragma unroll
            for (int mt = 0; mt < 4; mt++)
#pragma unroll
                for (int p = 0; p < 4; p++) {
                    mma16816(acc[mt][2 * p + 0], af[mt], bf[p][0], bf[p][2]);
                    mma16816(acc[mt][2 * p + 1], af[mt], bf[p][1], bf[p][3]);
                }
        }
        if (++st == STAGES) st = 0;
        // no trailing __syncthreads: next iter's top barrier protects stage reuse
    }

    // epilogue: +bias, fp32 stores
#pragma unroll
    for (int mt = 0; mt < 4; mt++) {
#pragma unroll
        for (int nt = 0; nt < 8; nt++) {
            int m0 = mbase + wm * 64 + mt * 16 + (lane >> 2);
            int n0 = nbase + wn * 64 + nt * 8 + (lane & 3) * 2;
            float b0 = bias[n0], b1 = bias[n0 + 1];
            float2 v0 = make_float2(acc[mt][nt][0] + b0, acc[mt][nt][1] + b1);
            float2 v1 = make_float2(acc[mt][nt][2] + b0, acc[mt][nt][3] + b1);
            *(float2*)(out + (size_t)m0 * ND + n0)       = v0;
            *(float2*)(out + (size_t)(m0 + 8) * ND + n0) = v1;
        }
    }
}

// ======================================================================
// launcher
// ======================================================================
extern "C" void kernel_launch(void* const* d_in, const int* in_sizes, int n_in,
                              void* d_out, int out_size) {
    const float* x    = (const float*)d_in[0];
    const float* S    = (const float*)d_in[1];
    // d_in[2] = H_block (unused; FWHT computed analytically)
    const float* w    = (const float*)d_in[3];
    const float* la   = (const float*)d_in[4];
    const float* lb   = (const float*)d_in[5];
    const float* bias = (const float*)d_in[6];
    float* out = (float*)d_out;

    static int inited = 0;
    if (!inited) {
        cudaFuncSetAttribute(gemm_hmma, cudaFuncAttributeMaxDynamicSharedMemorySize, GEMM_SMEM);
        cudaFuncSetAttribute(lorat3, cudaFuncAttributeMaxDynamicSharedMemorySize, LORAT_SMEM);
        inited = 1;
    }

    mkA3_kernel<<<RANK, 256>>>(la, S);
    convW_kernel<<<(ND * 516 + 255) / 256, 256>>>(w, lb);
    rotq2<<<MM, 256>>>(x, S);
    lorat3<<<MM / 32, 256, LORAT_SMEM>>>(x);
    gemm_hmma<<<dim3(ND / BN, MM / BM), 256, GEMM_SMEM>>>(bias, out);
}

// round 11
// speedup vs baseline: 1.3511x; 1.1261x over previous
#include <cuda_runtime.h>
#include <cuda_fp16.h>
#include <cstdint>

// ---------------- problem constants ----------------
#define MM      8192        // B*S
#define KD      4096        // D_IN
#define ND      4096        // D_OUT
#define RANK    32
#define KEXTP   4160        // 4096 + 32 (lora) + 32 (zero pad) -> 65 chunks of 64
#define HBS     128
#define INV_SQRT_HBS 0.08838834764831845f

// ---------------- device scratch (.bss zero-init; pad cols stay 0) ----------
__device__ __align__(16) __half g_Xext[(size_t)MM * KEXTP];
__device__ __align__(16) __half g_Wext[(size_t)ND * KEXTP];
__device__ __align__(16) __half g_Xrot[(size_t)MM * KD];    // rotated x, fp16 (unquantized)
__device__ __align__(16) __half g_Ah[(size_t)RANK * KD];    // UNrotated lora_a, fp16

// ======================= common PTX helpers =======================
__device__ __forceinline__ void cp16s(uint32_t saddr, const void* gaddr) {
    asm volatile("cp.async.cg.shared.global [%0], [%1], 16;" :: "r"(saddr), "l"(gaddr));
}
__device__ __forceinline__ void ldm4(uint32_t* r, uint32_t a) {
    asm volatile("ldmatrix.sync.aligned.m8n8.x4.shared.b16 {%0,%1,%2,%3}, [%4];"
        : "=r"(r[0]), "=r"(r[1]), "=r"(r[2]), "=r"(r[3]) : "r"(a));
}
__device__ __forceinline__ void mma16816(float* d, const uint32_t* a, uint32_t b0, uint32_t b1) {
    asm volatile("mma.sync.aligned.m16n8k16.row.col.f32.f16.f16.f32 "
        "{%0,%1,%2,%3},{%4,%5,%6,%7},{%8,%9},{%0,%1,%2,%3};"
        : "+f"(d[0]), "+f"(d[1]), "+f"(d[2]), "+f"(d[3])
        : "r"(a[0]), "r"(a[1]), "r"(a[2]), "r"(a[3]), "r"(b0), "r"(b1));
}

// ======================================================================
// P0a: Ah = fp16(lora_a)   (NO rotation — x_rot side already carries it;
//      t = x_rot @ lora_a^T matches the reference einsum exactly)
// ======================================================================
__global__ void convA_kernel(const float* __restrict__ la) {
    int idx = blockIdx.x * 256 + threadIdx.x;       // one 8-elem chunk
    if (idx >= RANK * KD / 8) return;
    const float* src = la + (size_t)idx * 8;
    float4 f0 = *(const float4*)(src);
    float4 f1 = *(const float4*)(src + 4);
    __half h[8];
    h[0]=__float2half_rn(f0.x); h[1]=__float2half_rn(f0.y);
    h[2]=__float2half_rn(f0.z); h[3]=__float2half_rn(f0.w);
    h[4]=__float2half_rn(f1.x); h[5]=__float2half_rn(f1.y);
    h[6]=__float2half_rn(f1.z); h[7]=__float2half_rn(f1.w);
    *(uint4*)(&g_Ah[(size_t)idx * 8]) = *(uint4*)h;
}

// ======================================================================
// P0b: Wext = [w_quantized | lora_b] as fp16 (pad cols remain zero)
// ======================================================================
__global__ void convW_kernel(const float* __restrict__ w, const float* __restrict__ lb) {
    int idx = blockIdx.x * 256 + threadIdx.x;
    const int chunks_per_row = 516;              // (4096+32)/8
    if (idx >= ND * chunks_per_row) return;
    int n = idx / chunks_per_row;
    int k = (idx - n * chunks_per_row) * 8;
    const float* src = (k < KD) ? (w + (size_t)n * KD + k)
                                : (lb + (size_t)n * RANK + (k - KD));
    float4 f0 = *(const float4*)(src);
    float4 f1 = *(const float4*)(src + 4);
    __half h[8];
    h[0]=__float2half_rn(f0.x); h[1]=__float2half_rn(f0.y);
    h[2]=__float2half_rn(f0.z); h[3]=__float2half_rn(f0.w);
    h[4]=__float2half_rn(f1.x); h[5]=__float2half_rn(f1.y);
    h[6]=__float2half_rn(f1.z); h[7]=__float2half_rn(f1.w);
    *(uint4*)(&g_Wext[(size_t)n * KEXTP + k]) = *(uint4*)h;
}

// ======================================================================
// P1: warp-per-128-block FWHT (shfl.bfly), NVFP4 quant -> Xext,
//     plus unquantized x_rot fp16 -> g_Xrot
// ======================================================================
__global__ __launch_bounds__(256) void rotq3(const float* __restrict__ x,
                                             const float* __restrict__ S) {
    const int r = blockIdx.x;
    const int w = threadIdx.x >> 5, lane = threadIdx.x & 31;
    const float* xr = x + (size_t)r * KD;
    __half* orow = g_Xext + (size_t)r * KEXTP;
    __half* rrow = g_Xrot + (size_t)r * KD;
#pragma unroll
    for (int hbi = 0; hbi < 4; hbi++) {
        const int base = (w * 4 + hbi) * HBS;
        float v[4];
#pragma unroll
        for (int i = 0; i < 4; i++) {
            int e = base + i * 32 + lane;
            v[i] = xr[e] * S[e];
        }
#pragma unroll
        for (int str = 1; str <= 16; str <<= 1) {
#pragma unroll
            for (int i = 0; i < 4; i++) {
                float o = __shfl_xor_sync(0xffffffffu, v[i], str);
                v[i] = (lane & str) ? (o - v[i]) : (v[i] + o);
            }
        }
        { float a=v[0],b=v[1]; v[0]=a+b; v[1]=a-b;
          float c=v[2],d=v[3]; v[2]=c+d; v[3]=c-d; }
        { float a=v[0],c=v[2]; v[0]=a+c; v[2]=a-c;
          float b=v[1],d=v[3]; v[1]=b+d; v[3]=b-d; }
#pragma unroll
        for (int i = 0; i < 4; i++) v[i] *= INV_SQRT_HBS;
#pragma unroll
        for (int i = 0; i < 4; i++)
            rrow[base + i * 32 + lane] = __float2half_rn(v[i]);
#pragma unroll
        for (int i = 0; i < 4; i++) {
            float m = fabsf(v[i]);
#pragma unroll
            for (int str = 1; str <= 8; str <<= 1)
                m = fmaxf(m, __shfl_xor_sync(0xffffffffu, m, str));
            m = fmaxf(m, 1e-12f);
            float scale = m / 6.0f;
            float av = fabsf(v[i]) / scale;
            float level;
            if      (av <= 0.25f) level = 0.0f;
            else if (av <= 0.75f) level = 0.5f;
            else if (av <= 1.25f) level = 1.0f;
            else if (av <= 1.75f) level = 1.5f;
            else if (av <= 2.50f) level = 2.0f;
            else if (av <= 3.50f) level = 3.0f;
            else if (av <= 5.00f) level = 4.0f;
            else                  level = 6.0f;
            float q = copysignf(level * scale, v[i]);
            orow[base + i * 32 + lane] = __float2half_rn(q);
        }
    }
}

// ======================================================================
// P2: t = x_rot @ lora_a^T (fp16 HMMA, fp32 accum) -> Xext[:, 4096:4128]
//     32-row tiles (grid 256), 8 warps K-sliced, smem cross-warp reduce
// ======================================================================
#define TSTR 136                          // padded tile stride (halves)
#define TSTG (2 * 32 * TSTR)              // A+B halves per stage (8704)
#define TLORA_SMEM (2 * TSTG * 2 < 32768 ? 32768 : 2 * TSTG * 2)  // 34816 B

__global__ __launch_bounds__(256) void tlora(int dummy) {
    extern __shared__ __half tsm[];
    float* red = (float*)tsm;             // 8*32*32 fp32 = 32KB (reused after loop)
    const int tid = threadIdx.x;
    const int w = tid >> 5, lane = tid & 31;
    const int rb = blockIdx.x * 32;
    const uint32_t sb = (uint32_t)__cvta_generic_to_shared(tsm);
    const int lrow = ((lane >> 3) & 1) * 8 + (lane & 7);
    const int lcol = (lane >> 4) * 8;

    float acc[2][4][4];
#pragma unroll
    for (int a = 0; a < 2; a++)
#pragma unroll
        for (int b = 0; b < 4; b++)
#pragma unroll
            for (int c = 0; c < 4; c++) acc[a][b][c] = 0.0f;

#define TLOAD(sg, c)                                                            \
    do {                                                                        \
        const int k0 = (c) * 128;                                               \
        const uint32_t ab = sb + (uint32_t)((sg) * TSTG) * 2;                   \
        const uint32_t bb = ab + (uint32_t)(32 * TSTR) * 2;                     \
        _Pragma("unroll")                                                       \
        for (int i = 0; i < 2; i++) {                                           \
            int cc = tid + i * 256;                                             \
            int row = cc >> 4, q = cc & 15;                                     \
            cp16s(ab + (uint32_t)(row * TSTR + q * 8) * 2,                      \
                  g_Xrot + (size_t)(rb + row) * KD + k0 + q * 8);               \
        }                                                                       \
        _Pragma("unroll")                                                       \
        for (int i = 0; i < 2; i++) {                                           \
            int cc = tid + i * 256;                                             \
            int row = cc >> 4, q = cc & 15;                                     \
            cp16s(bb + (uint32_t)(row * TSTR + q * 8) * 2,                      \
                  g_Ah + (size_t)row * KD + k0 + q * 8);                        \
        }                                                                       \
        asm volatile("cp.async.commit_group;");                                 \
    } while (0)

    TLOAD(0, 0);
    for (int c = 0; c < 32; c++) {
        if (c + 1 < 32) TLOAD((c + 1) & 1, c + 1);
        if (c + 1 < 32) asm volatile("cp.async.wait_group 1;");
        else            asm volatile("cp.async.wait_group 0;");
        __syncthreads();
        const uint32_t ab = sb + (uint32_t)((c & 1) * TSTG) * 2;
        const uint32_t bb = ab + (uint32_t)(32 * TSTR) * 2;
        const int kkw = w * 16;
        uint32_t af[2][4], bf[2][4];
#pragma unroll
        for (int mt = 0; mt < 2; mt++)
            ldm4(af[mt], ab + (uint32_t)((mt * 16 + lrow) * TSTR + kkw + lcol) * 2);
#pragma unroll
        for (int p = 0; p < 2; p++)
            ldm4(bf[p], bb + (uint32_t)((p * 16 + lrow) * TSTR + kkw + lcol) * 2);
#pragma unroll
        for (int mt = 0; mt < 2; mt++)
#pragma unroll
            for (int p = 0; p < 2; p++) {
                mma16816(acc[mt][2 * p + 0], af[mt], bf[p][0], bf[p][2]);
                mma16816(acc[mt][2 * p + 1], af[mt], bf[p][1], bf[p][3]);
            }
        __syncthreads();
    }

    // cross-warp reduction: red[w][row][col]
#pragma unroll
    for (int mt = 0; mt < 2; mt++)
#pragma unroll
        for (int nt = 0; nt < 4; nt++) {
            int r0 = mt * 16 + (lane >> 2);
            int c0 = nt * 8 + (lane & 3) * 2;
            red[w * 1024 + r0 * 32 + c0]           = acc[mt][nt][0];
            red[w * 1024 + r0 * 32 + c0 + 1]       = acc[mt][nt][1];
            red[w * 1024 + (r0 + 8) * 32 + c0]     = acc[mt][nt][2];
            red[w * 1024 + (r0 + 8) * 32 + c0 + 1] = acc[mt][nt][3];
        }
    __syncthreads();
    {
        const int idx = tid * 4;
        const int row = idx >> 5, col = idx & 31;
        float s[4];
#pragma unroll
        for (int j = 0; j < 4; j++) {
            float v = 0.0f;
#pragma unroll
            for (int ww = 0; ww < 8; ww++) v += red[ww * 1024 + idx + j];
            s[j] = v;
        }
        __half h[4];
        h[0]=__float2half_rn(s[0]); h[1]=__float2half_rn(s[1]);
        h[2]=__float2half_rn(s[2]); h[3]=__float2half_rn(s[3]);
        *(uint2*)&g_Xext[(size_t)(rb + row) * KEXTP + KD + col] = *(uint2*)h;
    }
}

// ======================================================================
// P3: GEMM out[8192,4096] = Xext @ Wext^T + bias
//     128x256 CTA, BK=64, 3-stage cp.async, 8 warps 64x64, frag dbl-buffer
// ======================================================================
#define BM 128
#define BN 256
#define BK 64
#define STAGES 3
#define SROW 72
#define NT (KEXTP / BK)                      // 65
#define ASTG (BM * SROW)
#define BSTG (BN * SROW)
#define STG  (ASTG + BSTG)
#define GEMM_SMEM (STAGES * STG * 2)         // 165888 B

__global__ __launch_bounds__(256, 1) void gemm_hmma(const float* __restrict__ bias,
                                                    float* __restrict__ out) {
    extern __shared__ __half smemh[];
    const int tid  = threadIdx.x;
    const int warp = tid >> 5, lane = tid & 31;
    const int wm = warp >> 2, wn = warp & 3;
    const int mbase = blockIdx.y * BM;
    const int nbase = blockIdx.x * BN;
    const __half* gA = g_Xext + (size_t)mbase * KEXTP;
    const __half* gB = g_Wext + (size_t)nbase * KEXTP;
    const uint32_t sbase = (uint32_t)__cvta_generic_to_shared(smemh);

    float acc[4][8][4];
#pragma unroll
    for (int a = 0; a < 4; a++)
#pragma unroll
        for (int b = 0; b < 8; b++)
#pragma unroll
            for (int c = 0; c < 4; c++) acc[a][b][c] = 0.0f;

    const int lrow = ((lane >> 3) & 1) * 8 + (lane & 7);
    const int lcol = (lane >> 4) * 8;

#define LOAD_STAGE(sg, t)                                                        \
    do {                                                                         \
        const int k0 = (t) * BK;                                                 \
        const uint32_t ab = sbase + (uint32_t)((sg) * STG) * 2;                  \
        const uint32_t bb = ab + ASTG * 2;                                       \
        _Pragma("unroll")                                                        \
        for (int i = 0; i < 4; i++) {                                            \
            int c = tid + i * 256;                                               \
            int row = c >> 3, q = c & 7;                                         \
            cp16s(ab + (uint32_t)(row * SROW + q * 8) * 2,                       \
                  gA + (size_t)row * KEXTP + k0 + q * 8);                        \
        }                                                                        \
        _Pragma("unroll")                                                        \
        for (int i = 0; i < 8; i++) {                                            \
            int c = tid + i * 256;                                               \
            int row = c >> 3, q = c & 7;                                         \
            cp16s(bb + (uint32_t)(row * SROW + q * 8) * 2,                       \
                  gB + (size_t)row * KEXTP + k0 + q * 8);                        \
        }                                                                        \
        asm volatile("cp.async.commit_group;");                                  \
    } while (0)

#define LOAD_FRAGS(buf, ab, bb, kk)                                              \
    do {                                                                         \
        _Pragma("unroll")                                                        \
        for (int mt = 0; mt < 4; mt++)                                           \
            ldm4(af[buf][mt], (ab) + (uint32_t)((wm * 64 + mt * 16 + lrow) * SROW + (kk) + lcol) * 2); \
        _Pragma("unroll")                                                        \
        for (int p = 0; p < 4; p++)                                              \
            ldm4(bf[buf][p], (bb) + (uint32_t)((wn * 64 + p * 16 + lrow) * SROW + (kk) + lcol) * 2);   \
    } while (0)

    LOAD_STAGE(0, 0);
    LOAD_STAGE(1, 1);

    uint32_t af[2][4][4], bf[2][4][4];
    int st = 0;
    for (int t = 0; t < NT; t++) {
        if (t + 1 < NT) asm volatile("cp.async.wait_group 1;");
        else            asm volatile("cp.async.wait_group 0;");
        __syncthreads();
        if (t + 2 < NT) {
            int ns = st + 2; if (ns >= STAGES) ns -= STAGES;
            LOAD_STAGE(ns, t + 2);
        }
        const uint32_t ab = sbase + (uint32_t)(st * STG) * 2;
        const uint32_t bb = ab + ASTG * 2;
        LOAD_FRAGS(0, ab, bb, 0);
#pragma unroll
        for (int ks = 0; ks < BK / 16; ks++) {
            const int cur = ks & 1;
            if (ks + 1 < BK / 16) LOAD_FRAGS(cur ^ 1, ab, bb, (ks + 1) * 16);
#pragma unroll
            for (int mt = 0; mt < 4; mt++)
#pragma unroll
                for (int p = 0; p < 4; p++) {
                    mma16816(acc[mt][2 * p + 0], af[cur][mt], bf[cur][p][0], bf[cur][p][2]);
                    mma16816(acc[mt][2 * p + 1], af[cur][mt], bf[cur][p][1], bf[cur][p][3]);
                }
        }
        if (++st == STAGES) st = 0;
    }

#pragma unroll
    for (int mt = 0; mt < 4; mt++) {
#pragma unroll
        for (int nt = 0; nt < 8; nt++) {
            int m0 = mbase + wm * 64 + mt * 16 + (lane >> 2);
            int n0 = nbase + wn * 64 + nt * 8 + (lane & 3) * 2;
            float b0 = bias[n0], b1 = bias[n0 + 1];
            float2 v0 = make_float2(acc[mt][nt][0] + b0, acc[mt][nt][1] + b1);
            float2 v1 = make_float2(acc[mt][nt][2] + b0, acc[mt][nt][3] + b1);
            *(float2*)(out + (size_t)m0 * ND + n0)       = v0;
            *(float2*)(out + (size_t)(m0 + 8) * ND + n0) = v1;
        }
    }
}

// ======================================================================
// launcher
// ======================================================================
extern "C" void kernel_launch(void* const* d_in, const int* in_sizes, int n_in,
                              void* d_out, int out_size) {
    const float* x    = (const float*)d_in[0];
    const float* S    = (const float*)d_in[1];
    // d_in[2] = H_block (unused; FWHT computed analytically)
    const float* w    = (const float*)d_in[3];
    const float* la   = (const float*)d_in[4];
    const float* lb   = (const float*)d_in[5];
    const float* bias = (const float*)d_in[6];
    float* out = (float*)d_out;

    static int inited = 0;
    if (!inited) {
        cudaFuncSetAttribute(gemm_hmma, cudaFuncAttributeMaxDynamicSharedMemorySize, GEMM_SMEM);
        cudaFuncSetAttribute(tlora, cudaFuncAttributeMaxDynamicSharedMemorySize, TLORA_SMEM);
        inited = 1;
    }

    convA_kernel<<<(RANK * KD / 8 + 255) / 256, 256>>>(la);
    convW_kernel<<<(ND * 516 + 255) / 256, 256>>>(w, lb);
    rotq3<<<MM, 256>>>(x, S);
    tlora<<<MM / 32, 256, TLORA_SMEM>>>(0);
    gemm_hmma<<<dim3(ND / BN, MM / BM), 256, GEMM_SMEM>>>(bias, out);
}

// round 14
// speedup vs baseline: 1.3959x; 1.0332x over previous
#include <cuda_runtime.h>
#include <cuda_fp16.h>
#include <cstdint>

// ---------------- problem constants ----------------
#define MM      8192        // B*S
#define KD      4096        // D_IN
#define ND      4096        // D_OUT
#define RANK    32
#define KEXTP   4160        // 4096 + 32 (lora) + 32 (zero pad) -> 65 chunks of 64
#define HBS     128
#define INV_SQRT_HBS 0.08838834764831845f

// ---------------- device scratch (.bss zero-init; pad cols stay 0) ----------
__device__ __align__(16) __half g_Xext[(size_t)MM * KEXTP];
__device__ __align__(16) __half g_Wext[(size_t)ND * KEXTP];
__device__ __align__(16) __half g_Xrot[(size_t)MM * KD];    // rotated x, fp16 (unquantized)
__device__ __align__(16) __half g_Ah[(size_t)RANK * KD];    // UNrotated lora_a, fp16

// ======================= common PTX helpers =======================
__device__ __forceinline__ void cp16s(uint32_t saddr, const void* gaddr) {
    asm volatile("cp.async.cg.shared.global [%0], [%1], 16;" :: "r"(saddr), "l"(gaddr));
}
__device__ __forceinline__ void ldm4(uint32_t* r, uint32_t a) {
    asm volatile("ldmatrix.sync.aligned.m8n8.x4.shared.b16 {%0,%1,%2,%3}, [%4];"
        : "=r"(r[0]), "=r"(r[1]), "=r"(r[2]), "=r"(r[3]) : "r"(a));
}
__device__ __forceinline__ void mma16816(float* d, const uint32_t* a, uint32_t b0, uint32_t b1) {
    asm volatile("mma.sync.aligned.m16n8k16.row.col.f32.f16.f16.f32 "
        "{%0,%1,%2,%3},{%4,%5,%6,%7},{%8,%9},{%0,%1,%2,%3};"
        : "+f"(d[0]), "+f"(d[1]), "+f"(d[2]), "+f"(d[3])
        : "r"(a[0]), "r"(a[1]), "r"(a[2]), "r"(a[3]), "r"(b0), "r"(b1));
}

// ======================================================================
// P0a: Ah = fp16(lora_a)   (NO rotation — x_rot side already carries it)
// ======================================================================
__global__ void convA_kernel(const float* __restrict__ la) {
    int idx = blockIdx.x * 256 + threadIdx.x;       // one 8-elem chunk
    if (idx >= RANK * KD / 8) return;
    const float* src = la + (size_t)idx * 8;
    float4 f0 = *(const float4*)(src);
    float4 f1 = *(const float4*)(src + 4);
    __half h[8];
    h[0]=__float2half_rn(f0.x); h[1]=__float2half_rn(f0.y);
    h[2]=__float2half_rn(f0.z); h[3]=__float2half_rn(f0.w);
    h[4]=__float2half_rn(f1.x); h[5]=__float2half_rn(f1.y);
    h[6]=__float2half_rn(f1.z); h[7]=__float2half_rn(f1.w);
    *(uint4*)(&g_Ah[(size_t)idx * 8]) = *(uint4*)h;
}

// ======================================================================
// P0b: Wext = [w_quantized | lora_b] as fp16 (pad cols remain zero)
// ======================================================================
__global__ void convW_kernel(const float* __restrict__ w, const float* __restrict__ lb) {
    int idx = blockIdx.x * 256 + threadIdx.x;
    const int chunks_per_row = 516;              // (4096+32)/8
    if (idx >= ND * chunks_per_row) return;
    int n = idx / chunks_per_row;
    int k = (idx - n * chunks_per_row) * 8;
    const float* src = (k < KD) ? (w + (size_t)n * KD + k)
                                : (lb + (size_t)n * RANK + (k - KD));
    float4 f0 = *(const float4*)(src);
    float4 f1 = *(const float4*)(src + 4);
    __half h[8];
    h[0]=__float2half_rn(f0.x); h[1]=__float2half_rn(f0.y);
    h[2]=__float2half_rn(f0.z); h[3]=__float2half_rn(f0.w);
    h[4]=__float2half_rn(f1.x); h[5]=__float2half_rn(f1.y);
    h[6]=__float2half_rn(f1.z); h[7]=__float2half_rn(f1.w);
    *(uint4*)(&g_Wext[(size_t)n * KEXTP + k]) = *(uint4*)h;
}

// ======================================================================
// P1: warp-per-128-block FWHT (shfl.bfly), NVFP4 quant -> Xext,
//     plus unquantized x_rot fp16 -> g_Xrot
// ======================================================================
__global__ __launch_bounds__(256) void rotq3(const float* __restrict__ x,
                                             const float* __restrict__ S) {
    const int r = blockIdx.x;
    const int w = threadIdx.x >> 5, lane = threadIdx.x & 31;
    const float* xr = x + (size_t)r * KD;
    __half* orow = g_Xext + (size_t)r * KEXTP;
    __half* rrow = g_Xrot + (size_t)r * KD;
#pragma unroll
    for (int hbi = 0; hbi < 4; hbi++) {
        const int base = (w * 4 + hbi) * HBS;
        float v[4];
#pragma unroll
        for (int i = 0; i < 4; i++) {
            int e = base + i * 32 + lane;
            v[i] = xr[e] * S[e];
        }
#pragma unroll
        for (int str = 1; str <= 16; str <<= 1) {
#pragma unroll
            for (int i = 0; i < 4; i++) {
                float o = __shfl_xor_sync(0xffffffffu, v[i], str);
                v[i] = (lane & str) ? (o - v[i]) : (v[i] + o);
            }
        }
        { float a=v[0],b=v[1]; v[0]=a+b; v[1]=a-b;
          float c=v[2],d=v[3]; v[2]=c+d; v[3]=c-d; }
        { float a=v[0],c=v[2]; v[0]=a+c; v[2]=a-c;
          float b=v[1],d=v[3]; v[1]=b+d; v[3]=b-d; }
#pragma unroll
        for (int i = 0; i < 4; i++) v[i] *= INV_SQRT_HBS;
#pragma unroll
        for (int i = 0; i < 4; i++)
            rrow[base + i * 32 + lane] = __float2half_rn(v[i]);
#pragma unroll
        for (int i = 0; i < 4; i++) {
            float m = fabsf(v[i]);
#pragma unroll
            for (int str = 1; str <= 8; str <<= 1)
                m = fmaxf(m, __shfl_xor_sync(0xffffffffu, m, str));
            m = fmaxf(m, 1e-12f);
            float scale = m / 6.0f;
            float av = fabsf(v[i]) / scale;
            float level;
            if      (av <= 0.25f) level = 0.0f;
            else if (av <= 0.75f) level = 0.5f;
            else if (av <= 1.25f) level = 1.0f;
            else if (av <= 1.75f) level = 1.5f;
            else if (av <= 2.50f) level = 2.0f;
            else if (av <= 3.50f) level = 3.0f;
            else if (av <= 5.00f) level = 4.0f;
            else                  level = 6.0f;
            float q = copysignf(level * scale, v[i]);
            orow[base + i * 32 + lane] = __float2half_rn(q);
        }
    }
}

// ======================================================================
// P2: t = x_rot @ lora_a^T (fp16 HMMA, fp32 accum) -> Xext[:, 4096:4128]
// ======================================================================
#define TSTR 136                          // padded tile stride (halves)
#define TSTG (2 * 32 * TSTR)              // A+B halves per stage (8704)
#define TLORA_SMEM (2 * TSTG * 2 < 32768 ? 32768 : 2 * TSTG * 2)  // 34816 B

__global__ __launch_bounds__(256) void tlora(int dummy) {
    extern __shared__ __half tsm[];
    float* red = (float*)tsm;             // 8*32*32 fp32 = 32KB (reused after loop)
    const int tid = threadIdx.x;
    const int w = tid >> 5, lane = tid & 31;
    const int rb = blockIdx.x * 32;
    const uint32_t sb = (uint32_t)__cvta_generic_to_shared(tsm);
    const int lrow = ((lane >> 3) & 1) * 8 + (lane & 7);
    const int lcol = (lane >> 4) * 8;

    float acc[2][4][4];
#pragma unroll
    for (int a = 0; a < 2; a++)
#pragma unroll
        for (int b = 0; b < 4; b++)
#pragma unroll
            for (int c = 0; c < 4; c++) acc[a][b][c] = 0.0f;

#define TLOAD(sg, c)                                                            \
    do {                                                                        \
        const int k0 = (c) * 128;                                               \
        const uint32_t ab = sb + (uint32_t)((sg) * TSTG) * 2;                   \
        const uint32_t bb = ab + (uint32_t)(32 * TSTR) * 2;                     \
        _Pragma("unroll")                                                       \
        for (int i = 0; i < 2; i++) {                                           \
            int cc = tid + i * 256;                                             \
            int row = cc >> 4, q = cc & 15;                                     \
            cp16s(ab + (uint32_t)(row * TSTR + q * 8) * 2,                      \
                  g_Xrot + (size_t)(rb + row) * KD + k0 + q * 8);               \
        }                                                                       \
        _Pragma("unroll")                                                       \
        for (int i = 0; i < 2; i++) {                                           \
            int cc = tid + i * 256;                                             \
            int row = cc >> 4, q = cc & 15;                                     \
            cp16s(bb + (uint32_t)(row * TSTR + q * 8) * 2,                      \
                  g_Ah + (size_t)row * KD + k0 + q * 8);                        \
        }                                                                       \
        asm volatile("cp.async.commit_group;");                                 \
    } while (0)

    TLOAD(0, 0);
    for (int c = 0; c < 32; c++) {
        if (c + 1 < 32) TLOAD((c + 1) & 1, c + 1);
        if (c + 1 < 32) asm volatile("cp.async.wait_group 1;");
        else            asm volatile("cp.async.wait_group 0;");
        __syncthreads();
        const uint32_t ab = sb + (uint32_t)((c & 1) * TSTG) * 2;
        const uint32_t bb = ab + (uint32_t)(32 * TSTR) * 2;
        const int kkw = w * 16;
        uint32_t af[2][4], bf[2][4];
#pragma unroll
        for (int mt = 0; mt < 2; mt++)
            ldm4(af[mt], ab + (uint32_t)((mt * 16 + lrow) * TSTR + kkw + lcol) * 2);
#pragma unroll
        for (int p = 0; p < 2; p++)
            ldm4(bf[p], bb + (uint32_t)((p * 16 + lrow) * TSTR + kkw + lcol) * 2);
#pragma unroll
        for (int mt = 0; mt < 2; mt++)
#pragma unroll
            for (int p = 0; p < 2; p++) {
                mma16816(acc[mt][2 * p + 0], af[mt], bf[p][0], bf[p][2]);
                mma16816(acc[mt][2 * p + 1], af[mt], bf[p][1], bf[p][3]);
            }
        __syncthreads();
    }

#pragma unroll
    for (int mt = 0; mt < 2; mt++)
#pragma unroll
        for (int nt = 0; nt < 4; nt++) {
            int r0 = mt * 16 + (lane >> 2);
            int c0 = nt * 8 + (lane & 3) * 2;
            red[w * 1024 + r0 * 32 + c0]           = acc[mt][nt][0];
            red[w * 1024 + r0 * 32 + c0 + 1]       = acc[mt][nt][1];
            red[w * 1024 + (r0 + 8) * 32 + c0]     = acc[mt][nt][2];
            red[w * 1024 + (r0 + 8) * 32 + c0 + 1] = acc[mt][nt][3];
        }
    __syncthreads();
    {
        const int idx = tid * 4;
        const int row = idx >> 5, col = idx & 31;
        float s[4];
#pragma unroll
        for (int j = 0; j < 4; j++) {
            float v = 0.0f;
#pragma unroll
            for (int ww = 0; ww < 8; ww++) v += red[ww * 1024 + idx + j];
            s[j] = v;
        }
        __half h[4];
        h[0]=__float2half_rn(s[0]); h[1]=__float2half_rn(s[1]);
        h[2]=__float2half_rn(s[2]); h[3]=__float2half_rn(s[3]);
        *(uint2*)&g_Xext[(size_t)(rb + row) * KEXTP + KD + col] = *(uint2*)h;
    }
}

// ======================================================================
// P3: GEMM out[8192,4096] = Xext @ Wext^T + bias
//     128x256 CTA tile, BK=64, 3-stage cp.async, **512 threads**:
//     16 warps (4/SMSP) of 32x64 each — occupancy axis, traffic unchanged
// ======================================================================
#define BM 128
#define BN 256
#define BK 64
#define STAGES 3
#define SROW 72
#define NT (KEXTP / BK)                      // 65
#define ASTG (BM * SROW)
#define BSTG (BN * SROW)
#define STG  (ASTG + BSTG)
#define GEMM_SMEM (STAGES * STG * 2)         // 165888 B

__global__ __launch_bounds__(512, 1) void gemm_hmma(const float* __restrict__ bias,
                                                    float* __restrict__ out) {
    extern __shared__ __half smemh[];
    const int tid  = threadIdx.x;
    const int warp = tid >> 5, lane = tid & 31;
    const int wm = warp >> 2, wn = warp & 3;      // 4 x 4 warp grid, tile 32x64
    const int mbase = blockIdx.y * BM;
    const int nbase = blockIdx.x * BN;
    const __half* gA = g_Xext + (size_t)mbase * KEXTP;
    const __half* gB = g_Wext + (size_t)nbase * KEXTP;
    const uint32_t sbase = (uint32_t)__cvta_generic_to_shared(smemh);

    float acc[2][8][4];
#pragma unroll
    for (int a = 0; a < 2; a++)
#pragma unroll
        for (int b = 0; b < 8; b++)
#pragma unroll
            for (int c = 0; c < 4; c++) acc[a][b][c] = 0.0f;

    const int lrow = ((lane >> 3) & 1) * 8 + (lane & 7);
    const int lcol = (lane >> 4) * 8;

#define LOAD_STAGE(sg, t)                                                        \
    do {                                                                         \
        const int k0 = (t) * BK;                                                 \
        const uint32_t ab = sbase + (uint32_t)((sg) * STG) * 2;                  \
        const uint32_t bb = ab + ASTG * 2;                                       \
        _Pragma("unroll")                                                        \
        for (int i = 0; i < 2; i++) {                                            \
            int c = tid + i * 512;                                               \
            int row = c >> 3, q = c & 7;                                         \
            cp16s(ab + (uint32_t)(row * SROW + q * 8) * 2,                       \
                  gA + (size_t)row * KEXTP + k0 + q * 8);                        \
        }                                                                        \
        _Pragma("unroll")                                                        \
        for (int i = 0; i < 4; i++) {                                            \
            int c = tid + i * 512;                                               \
            int row = c >> 3, q = c & 7;                                         \
            cp16s(bb + (uint32_t)(row * SROW + q * 8) * 2,                       \
                  gB + (size_t)row * KEXTP + k0 + q * 8);                        \
        }                                                                        \
        asm volatile("cp.async.commit_group;");                                  \
    } while (0)

#define LOAD_FRAGS(buf, ab, bb, kk)                                              \
    do {                                                                         \
        _Pragma("unroll")                                                        \
        for (int mt = 0; mt < 2; mt++)                                           \
            ldm4(af[buf][mt], (ab) + (uint32_t)((wm * 32 + mt * 16 + lrow) * SROW + (kk) + lcol) * 2); \
        _Pragma("unroll")                                                        \
        for (int p = 0; p < 4; p++)                                              \
            ldm4(bf[buf][p], (bb) + (uint32_t)((wn * 64 + p * 16 + lrow) * SROW + (kk) + lcol) * 2);   \
    } while (0)

    LOAD_STAGE(0, 0);
    LOAD_STAGE(1, 1);

    uint32_t af[2][2][4], bf[2][4][4];
    int st = 0;
    for (int t = 0; t < NT; t++) {
        if (t + 1 < NT) asm volatile("cp.async.wait_group 1;");
        else            asm volatile("cp.async.wait_group 0;");
        __syncthreads();
        if (t + 2 < NT) {
            int ns = st + 2; if (ns >= STAGES) ns -= STAGES;
            LOAD_STAGE(ns, t + 2);
        }
        const uint32_t ab = sbase + (uint32_t)(st * STG) * 2;
        const uint32_t bb = ab + ASTG * 2;
        LOAD_FRAGS(0, ab, bb, 0);
#pragma unroll
        for (int ks = 0; ks < BK / 16; ks++) {
            const int cur = ks & 1;
            if (ks + 1 < BK / 16) LOAD_FRAGS(cur ^ 1, ab, bb, (ks + 1) * 16);
#pragma unroll
            for (int mt = 0; mt < 2; mt++)
#pragma unroll
                for (int p = 0; p < 4; p++) {
                    mma16816(acc[mt][2 * p + 0], af[cur][mt], bf[cur][p][0], bf[cur][p][2]);
                    mma16816(acc[mt][2 * p + 1], af[cur][mt], bf[cur][p][1], bf[cur][p][3]);
                }
        }
        if (++st == STAGES) st = 0;
    }

    // epilogue: +bias, fp32 stores
#pragma unroll
    for (int mt = 0; mt < 2; mt++) {
#pragma unroll
        for (int nt = 0; nt < 8; nt++) {
            int m0 = mbase + wm * 32 + mt * 16 + (lane >> 2);
            int n0 = nbase + wn * 64 + nt * 8 + (lane & 3) * 2;
            float b0 = bias[n0], b1 = bias[n0 + 1];
            float2 v0 = make_float2(acc[mt][nt][0] + b0, acc[mt][nt][1] + b1);
            float2 v1 = make_float2(acc[mt][nt][2] + b0, acc[mt][nt][3] + b1);
            *(float2*)(out + (size_t)m0 * ND + n0)       = v0;
            *(float2*)(out + (size_t)(m0 + 8) * ND + n0) = v1;
        }
    }
}

// ======================================================================
// launcher
// ======================================================================
extern "C" void kernel_launch(void* const* d_in, const int* in_sizes, int n_in,
                              void* d_out, int out_size) {
    const float* x    = (const float*)d_in[0];
    const float* S    = (const float*)d_in[1];
    // d_in[2] = H_block (unused; FWHT computed analytically)
    const float* w    = (const float*)d_in[3];
    const float* la   = (const float*)d_in[4];
    const float* lb   = (const float*)d_in[5];
    const float* bias = (const float*)d_in[6];
    float* out = (float*)d_out;

    static int inited = 0;
    if (!inited) {
        cudaFuncSetAttribute(gemm_hmma, cudaFuncAttributeMaxDynamicSharedMemorySize, GEMM_SMEM);
        cudaFuncSetAttribute(tlora, cudaFuncAttributeMaxDynamicSharedMemorySize, TLORA_SMEM);
        inited = 1;
    }

    convA_kernel<<<(RANK * KD / 8 + 255) / 256, 256>>>(la);
    convW_kernel<<<(ND * 516 + 255) / 256, 256>>>(w, lb);
    rotq3<<<MM, 256>>>(x, S);
    tlora<<<MM / 32, 256, TLORA_SMEM>>>(0);
    gemm_hmma<<<dim3(ND / BN, MM / BM), 512, GEMM_SMEM>>>(bias, out);
}